// round 8
// baseline (speedup 1.0000x reference)
#include <cuda_runtime.h>
#include <cstdint>

#define NN   50000
#define F    128
#define NCLS 40
#define MAXE 600000
#define SCB  512
#define NSB  ((NN + SCB - 1) / SCB)   // 98

// ---------------- scratch (__device__ globals; no allocations) -------------
__device__ float g_pt[NN * 256];     // layer1: [p|t] (stride 256); layer2: [q|u] (stride 80)
__device__ float g_h[NN * F];        // hidden activations
__device__ float g_wcat[F * 256];    // [w1l | w1r]
__device__ float g_wcat2[F * 80];    // [w2l | w2r]
__device__ int g_src[MAXE], g_dst[MAXE], g_csr[MAXE];
__device__ int g_cnt[NN], g_offs[NN], g_incl[NN];
__device__ int g_bsum[NSB], g_bexc[NSB];
__device__ int g_mode32;

// ---------------------------------------------------------------------------
__global__ void detect_kernel(const void* ei) {
    if (threadIdx.x == 0 && blockIdx.x == 0) {
        const long long* p = (const long long*)ei;
        int m32 = 0;
        for (int i = 0; i < 16; i++) {
            long long v = p[i];
            if (v < 0 || v >= NN) { m32 = 1; break; }
        }
        g_mode32 = m32;
    }
}

__global__ void zero_int_kernel(int4* a, int n4) {
    int i = blockIdx.x * blockDim.x + threadIdx.x;
    int stride = gridDim.x * blockDim.x;
    int4 z = make_int4(0, 0, 0, 0);
    for (; i < n4; i += stride) a[i] = z;
}

__global__ void build_wcat_kernel(const float* __restrict__ w1l,
                                  const float* __restrict__ w1r,
                                  const float* __restrict__ w2l,
                                  const float* __restrict__ w2r,
                                  float* __restrict__ wcat,
                                  float* __restrict__ wcat2) {
    int i = blockIdx.x * blockDim.x + threadIdx.x;
    if (i < F * 256) {
        int k = i >> 8, c = i & 255;
        wcat[i] = (c < 128) ? w1l[k * 128 + c] : w1r[k * 128 + (c - 128)];
    } else if (i < F * 256 + F * 80) {
        int j = i - F * 256;
        int k = j / 80, c = j % 80;
        wcat2[j] = (c < NCLS) ? w2l[k * NCLS + c] : w2r[k * NCLS + (c - NCLS)];
    }
}

__global__ void hist_kernel(const void* __restrict__ ei,
                            int* __restrict__ src32, int* __restrict__ dst32,
                            int* __restrict__ cnt, int E) {
    const int mode32 = g_mode32;
    int stride = gridDim.x * blockDim.x;
    for (int e = blockIdx.x * blockDim.x + threadIdx.x; e < E; e += stride) {
        int s, d;
        if (mode32) {
            const int* p = (const int*)ei;
            s = p[e]; d = p[E + e];
        } else {
            const long long* p = (const long long*)ei;
            s = (int)p[e]; d = (int)p[E + e];
        }
        src32[e] = s;
        dst32[e] = d;
        atomicAdd(&cnt[d], 1);
    }
}

__global__ void scan1_kernel(const int* __restrict__ cnt,
                             int* __restrict__ incl, int* __restrict__ bsum) {
    __shared__ int sm[SCB];
    int t = threadIdx.x;
    int i = blockIdx.x * SCB + t;
    int v = (i < NN) ? cnt[i] : 0;
    sm[t] = v;
    __syncthreads();
    for (int off = 1; off < SCB; off <<= 1) {
        int x = (t >= off) ? sm[t - off] : 0;
        __syncthreads();
        sm[t] += x;
        __syncthreads();
    }
    if (i < NN) incl[i] = sm[t];
    if (t == SCB - 1) bsum[blockIdx.x] = sm[t];
}

__global__ void scan2_kernel(const int* __restrict__ bsum, int* __restrict__ bexc) {
    __shared__ int sm[128];
    int t = threadIdx.x;
    int v = (t < NSB) ? bsum[t] : 0;
    sm[t] = v;
    __syncthreads();
    for (int off = 1; off < 128; off <<= 1) {
        int x = (t >= off) ? sm[t - off] : 0;
        __syncthreads();
        sm[t] += x;
        __syncthreads();
    }
    if (t < NSB) bexc[t] = sm[t] - v;
}

__global__ void scan3_kernel(const int* __restrict__ incl,
                             const int* __restrict__ cnt,
                             const int* __restrict__ bexc,
                             int* __restrict__ offs) {
    int i = blockIdx.x * blockDim.x + threadIdx.x;
    if (i < NN) offs[i] = incl[i] - cnt[i] + bexc[i >> 9];
}

__global__ void fill_kernel(const int* __restrict__ src32,
                            const int* __restrict__ dst32,
                            int* __restrict__ offs, int* __restrict__ csr, int E) {
    int stride = gridDim.x * blockDim.x;
    for (int e = blockIdx.x * blockDim.x + threadIdx.x; e < E; e += stride) {
        int d = dst32[e];
        int slot = atomicAdd(&offs[d], 1);
        csr[slot] = src32[e];
    }
}

// ---------------------------------------------------------------------------
// 3xTF32 tensor-core GEMM with hi/lo precomputed at tile-load time.
// Smem holds (hi,lo) uint2 pairs: As[128][KP], Bs[BN][KP] (n-major), KP=36
// (row stride 72 words == 8 mod 32 -> conflict-free LDS.64 fragments).
// K staged in 4 slices of 32. 8 warps: 4(m) x 2(n); warp tile 32 x BN/2.
__device__ __forceinline__ uint2 f2tf32p(float a) {
    uint2 r;
    asm("cvt.rna.tf32.f32 %0, %1;" : "=r"(r.x) : "f"(a));
    float t = a - __uint_as_float(r.x);
    asm("cvt.rna.tf32.f32 %0, %1;" : "=r"(r.y) : "f"(t));
    return r;
}

#define MMA_TF32(c, a0, a1, a2, a3, b0, b1)                                 \
    asm volatile(                                                           \
        "mma.sync.aligned.m16n8k8.row.col.f32.tf32.tf32.f32 "               \
        "{%0,%1,%2,%3},{%4,%5,%6,%7},{%8,%9},{%0,%1,%2,%3};"                \
        : "+f"((c)[0]), "+f"((c)[1]), "+f"((c)[2]), "+f"((c)[3])            \
        : "r"(a0), "r"(a1), "r"(a2), "r"(a3), "r"(b0), "r"(b1))

template <int BN, int SWB, int SWC>
__global__ __launch_bounds__(256, 2)
void gemm_tc_kernel(const float* __restrict__ A,
                    const float* __restrict__ B,
                    float* __restrict__ C,
                    int Nrows) {
    constexpr int NWT = BN / 16;       // 8-wide n-tiles per warp
    constexpr int KP = 36;             // padded uint2 stride for K-slice of 32
    extern __shared__ uint2 smu[];
    uint2* As = smu;                   // [128][KP]
    uint2* Bs = smu + 128 * KP;        // [BN][KP]

    int tid = threadIdx.x;
    int lane = tid & 31;
    int warp = tid >> 5;
    int g = lane >> 2, tig = lane & 3;
    int warpRow = warp & 3, warpCol = warp >> 2;
    int brow = blockIdx.x * 128;
    int colbase = blockIdx.y * 128;

    float acc[2][NWT][4];
#pragma unroll
    for (int mt = 0; mt < 2; mt++)
#pragma unroll
        for (int nt = 0; nt < NWT; nt++)
#pragma unroll
            for (int j = 0; j < 4; j++) acc[mt][nt][j] = 0.0f;

#pragma unroll
    for (int ks = 0; ks < 4; ks++) {
        int kc = ks * 32;
        if (ks) __syncthreads();
        // --- A slice (128 x 32): 4 float4 per thread, convert, store uint2
#pragma unroll
        for (int p = 0; p < 4; p++) {
            int idx = tid + p * 256;          // 0..1023
            int m = idx >> 3;
            int kq = (idx & 7) << 2;
            float4 v = make_float4(0.f, 0.f, 0.f, 0.f);
            if (brow + m < Nrows)
                v = *(const float4*)(A + (size_t)(brow + m) * F + kc + kq);
            uint2* dst = As + m * KP + kq;
            dst[0] = f2tf32p(v.x);
            dst[1] = f2tf32p(v.y);
            dst[2] = f2tf32p(v.z);
            dst[3] = f2tf32p(v.w);
        }
        // --- B slice (32 x BN) transposed into Bs[n][k]
        constexpr int BF4 = 8 * BN;           // float4 count
#pragma unroll
        for (int p = 0; p < (BF4 + 255) / 256; p++) {
            int idx = tid + p * 256;
            if (idx < BF4) {
                int kk = idx / (BN / 4);
                int n4 = (idx % (BN / 4)) * 4;
                float4 v = *(const float4*)(B + (size_t)(kc + kk) * SWB + colbase + n4);
                Bs[(n4 + 0) * KP + kk] = f2tf32p(v.x);
                Bs[(n4 + 1) * KP + kk] = f2tf32p(v.y);
                Bs[(n4 + 2) * KP + kk] = f2tf32p(v.z);
                Bs[(n4 + 3) * KP + kk] = f2tf32p(v.w);
            }
        }
        __syncthreads();

#pragma unroll
        for (int k8 = 0; k8 < 4; k8++) {
            int kb = k8 * 8;
            uint2 a0[2], a1[2], a2[2], a3[2];
#pragma unroll
            for (int mt = 0; mt < 2; mt++) {
                const uint2* ap = As + (warpRow * 32 + mt * 16 + g) * KP + kb;
                a0[mt] = ap[tig];
                a1[mt] = ap[8 * KP + tig];
                a2[mt] = ap[tig + 4];
                a3[mt] = ap[8 * KP + tig + 4];
            }
#pragma unroll
            for (int nt = 0; nt < NWT; nt++) {
                const uint2* bp = Bs + (warpCol * (BN / 2) + nt * 8 + g) * KP + kb;
                uint2 b0 = bp[tig];
                uint2 b1 = bp[tig + 4];
#pragma unroll
                for (int mt = 0; mt < 2; mt++) {
                    MMA_TF32(acc[mt][nt], a0[mt].x, a1[mt].x, a2[mt].x, a3[mt].x, b0.x, b1.x);
                    MMA_TF32(acc[mt][nt], a0[mt].x, a1[mt].x, a2[mt].x, a3[mt].x, b0.y, b1.y);
                    MMA_TF32(acc[mt][nt], a0[mt].y, a1[mt].y, a2[mt].y, a3[mt].y, b0.x, b1.x);
                }
            }
        }
    }

    // epilogue: c0,c1 = (row, 2tig..2tig+1), c2,c3 = (row+8, ...)
#pragma unroll
    for (int mt = 0; mt < 2; mt++) {
#pragma unroll
        for (int nt = 0; nt < NWT; nt++) {
            int row0 = brow + warpRow * 32 + mt * 16 + g;
            int col = colbase + warpCol * (BN / 2) + nt * 8 + 2 * tig;
            if (row0 < Nrows) {
                float2 v = make_float2(acc[mt][nt][0], acc[mt][nt][1]);
                *(float2*)(C + (size_t)row0 * SWC + col) = v;
            }
            if (row0 + 8 < Nrows) {
                float2 v = make_float2(acc[mt][nt][2], acc[mt][nt][3]);
                *(float2*)(C + (size_t)(row0 + 8) * SWC + col) = v;
            }
        }
    }
}

// ---------------------------------------------------------------------------
// Layer-1 aggregation + epilogue: h[n] = relu(mean_{s in N(n)} p[s] + t[n] + b1)
__global__ void agg1_kernel(const int* __restrict__ csr,
                            const int* __restrict__ offs,
                            const int* __restrict__ cnt,
                            const float* __restrict__ pt,
                            const float* __restrict__ b1,
                            float* __restrict__ h) {
    int gw = (blockIdx.x * blockDim.x + threadIdx.x) >> 5;
    int lane = threadIdx.x & 31;
    if (gw >= NN) return;
    int dg = cnt[gw];
    int beg = offs[gw] - dg;
    float4 acc0 = make_float4(0.f, 0.f, 0.f, 0.f);
    float4 acc1 = make_float4(0.f, 0.f, 0.f, 0.f);
    int i = 0;
    for (; i + 4 <= dg; i += 4) {
        int s0 = __ldg(&csr[beg + i]);
        int s1 = __ldg(&csr[beg + i + 1]);
        int s2 = __ldg(&csr[beg + i + 2]);
        int s3 = __ldg(&csr[beg + i + 3]);
        float4 v0 = *(const float4*)(pt + (long long)s0 * 256 + lane * 4);
        float4 v1 = *(const float4*)(pt + (long long)s1 * 256 + lane * 4);
        float4 v2 = *(const float4*)(pt + (long long)s2 * 256 + lane * 4);
        float4 v3 = *(const float4*)(pt + (long long)s3 * 256 + lane * 4);
        acc0.x += v0.x + v1.x; acc0.y += v0.y + v1.y;
        acc0.z += v0.z + v1.z; acc0.w += v0.w + v1.w;
        acc1.x += v2.x + v3.x; acc1.y += v2.y + v3.y;
        acc1.z += v2.z + v3.z; acc1.w += v2.w + v3.w;
    }
    for (; i < dg; i++) {
        int s = __ldg(&csr[beg + i]);
        float4 v = *(const float4*)(pt + (long long)s * 256 + lane * 4);
        acc0.x += v.x; acc0.y += v.y; acc0.z += v.z; acc0.w += v.w;
    }
    float inv = 1.0f / fmaxf((float)dg, 1.0f);
    float4 t = *(const float4*)(pt + (long long)gw * 256 + 128 + lane * 4);
    float4 bb = *(const float4*)(b1 + lane * 4);
    float4 r;
    r.x = fmaxf((acc0.x + acc1.x) * inv + t.x + bb.x, 0.f);
    r.y = fmaxf((acc0.y + acc1.y) * inv + t.y + bb.y, 0.f);
    r.z = fmaxf((acc0.z + acc1.z) * inv + t.z + bb.z, 0.f);
    r.w = fmaxf((acc0.w + acc1.w) * inv + t.w + bb.w, 0.f);
    *(float4*)(h + (long long)gw * F + lane * 4) = r;
}

// Layer-2: out[n] = mean q[s] + u[n] + b2. qu stride 80: q=0:40, u=40:80.
__global__ void agg2_kernel(const int* __restrict__ csr,
                            const int* __restrict__ offs,
                            const int* __restrict__ cnt,
                            const float* __restrict__ qu,
                            const float* __restrict__ b2,
                            float* __restrict__ out) {
    int gw = (blockIdx.x * blockDim.x + threadIdx.x) >> 5;
    int lane = threadIdx.x & 31;
    if (gw >= NN) return;
    int dg = cnt[gw];
    int beg = offs[gw] - dg;
    if (lane < 10) {
        float4 acc0 = make_float4(0.f, 0.f, 0.f, 0.f);
        float4 acc1 = make_float4(0.f, 0.f, 0.f, 0.f);
        int i = 0;
        for (; i + 4 <= dg; i += 4) {
            int s0 = __ldg(&csr[beg + i]);
            int s1 = __ldg(&csr[beg + i + 1]);
            int s2 = __ldg(&csr[beg + i + 2]);
            int s3 = __ldg(&csr[beg + i + 3]);
            float4 v0 = *(const float4*)(qu + (long long)s0 * 80 + lane * 4);
            float4 v1 = *(const float4*)(qu + (long long)s1 * 80 + lane * 4);
            float4 v2 = *(const float4*)(qu + (long long)s2 * 80 + lane * 4);
            float4 v3 = *(const float4*)(qu + (long long)s3 * 80 + lane * 4);
            acc0.x += v0.x + v1.x; acc0.y += v0.y + v1.y;
            acc0.z += v0.z + v1.z; acc0.w += v0.w + v1.w;
            acc1.x += v2.x + v3.x; acc1.y += v2.y + v3.y;
            acc1.z += v2.z + v3.z; acc1.w += v2.w + v3.w;
        }
        for (; i < dg; i++) {
            int s = __ldg(&csr[beg + i]);
            float4 v = *(const float4*)(qu + (long long)s * 80 + lane * 4);
            acc0.x += v.x; acc0.y += v.y; acc0.z += v.z; acc0.w += v.w;
        }
        float inv = 1.0f / fmaxf((float)dg, 1.0f);
        float4 uv = *(const float4*)(qu + (long long)gw * 80 + NCLS + lane * 4);
        float4 bb = *(const float4*)(b2 + lane * 4);
        float4 r;
        r.x = (acc0.x + acc1.x) * inv + uv.x + bb.x;
        r.y = (acc0.y + acc1.y) * inv + uv.y + bb.y;
        r.z = (acc0.z + acc1.z) * inv + uv.z + bb.z;
        r.w = (acc0.w + acc1.w) * inv + uv.w + bb.w;
        *(float4*)(out + (long long)gw * NCLS + lane * 4) = r;
    }
}

// ---------------------------------------------------------------------------
extern "C" void kernel_launch(void* const* d_in, const int* in_sizes, int n_in,
                              void* d_out, int out_size) {
    const float* x   = (const float*)d_in[0];
    const void*  ei  = d_in[1];
    const float* w1l = (const float*)d_in[2];
    const float* w1r = (const float*)d_in[3];
    const float* b1  = (const float*)d_in[4];
    const float* w2l = (const float*)d_in[5];
    const float* w2r = (const float*)d_in[6];
    const float* b2  = (const float*)d_in[7];
    float* out = (float*)d_out;

    int E = in_sizes[1] / 2;
    int N = in_sizes[0] / F;   // 50000

    float *pPT, *pH, *pWcat, *pWcat2;
    int *pSrc, *pDst, *pCsr, *pCnt, *pOffs, *pIncl, *pBsum, *pBexc;
    cudaGetSymbolAddress((void**)&pPT,    g_pt);
    cudaGetSymbolAddress((void**)&pH,     g_h);
    cudaGetSymbolAddress((void**)&pWcat,  g_wcat);
    cudaGetSymbolAddress((void**)&pWcat2, g_wcat2);
    cudaGetSymbolAddress((void**)&pSrc,   g_src);
    cudaGetSymbolAddress((void**)&pDst,   g_dst);
    cudaGetSymbolAddress((void**)&pCsr,   g_csr);
    cudaGetSymbolAddress((void**)&pCnt,   g_cnt);
    cudaGetSymbolAddress((void**)&pOffs,  g_offs);
    cudaGetSymbolAddress((void**)&pIncl,  g_incl);
    cudaGetSymbolAddress((void**)&pBsum,  g_bsum);
    cudaGetSymbolAddress((void**)&pBexc,  g_bexc);

    const int T = 256;
    int gemm_rows = (N + 127) / 128;          // 391
    int edge_blocks = (E + T - 1) / T;        // 2344
    int warp_blocks = (N * 32 + T - 1) / T;   // 6250

    // dynamic smem opt-in for the tensor-core GEMMs
    const int SMEM1 = (128 + 128) * 36 * 8;   // 73728
    const int SMEM2 = (128 + 80) * 36 * 8;    // 59904
    cudaFuncSetAttribute(gemm_tc_kernel<128, 256, 256>,
                         cudaFuncAttributeMaxDynamicSharedMemorySize, SMEM1);
    cudaFuncSetAttribute(gemm_tc_kernel<80, 80, 80>,
                         cudaFuncAttributeMaxDynamicSharedMemorySize, SMEM2);

    // Fork-join resources (host-side only; created per call, not destroyed).
    cudaStream_t s2 = 0;
    cudaEvent_t eA = 0, eB = 0;
    bool forked = (cudaStreamCreateWithFlags(&s2, cudaStreamNonBlocking) == cudaSuccess);
    if (forked) forked = (cudaEventCreateWithFlags(&eA, cudaEventDisableTiming) == cudaSuccess);
    if (forked) forked = (cudaEventCreateWithFlags(&eB, cudaEventDisableTiming) == cudaSuccess);
    cudaStream_t sb = forked ? s2 : (cudaStream_t)0;

    // --- main stream: 1 detect, 2 zero, 3 wcat ---
    detect_kernel<<<1, 32>>>(ei);
    zero_int_kernel<<<64, T>>>((int4*)pCnt, NN / 4 + 1);
    build_wcat_kernel<<<(F * 256 + F * 80 + T - 1) / T, T>>>(
        w1l, w1r, w2l, w2r, pWcat, pWcat2);

    // fork
    if (forked) {
        cudaEventRecord(eA, 0);
        cudaStreamWaitEvent(s2, eA, 0);
    }

    // 4: layer-1 tensor-core GEMM (profiled launch)
    gemm_tc_kernel<128, 256, 256><<<dim3(gemm_rows, 2), T, SMEM1>>>(
        x, pWcat, pPT, N);

    // CSR chain on branch stream (overlaps gemm1)
    hist_kernel<<<edge_blocks, T, 0, sb>>>(ei, pSrc, pDst, pCnt, E);
    scan1_kernel<<<NSB, SCB, 0, sb>>>(pCnt, pIncl, pBsum);
    scan2_kernel<<<1, 128, 0, sb>>>(pBsum, pBexc);
    scan3_kernel<<<(NN + T - 1) / T, T, 0, sb>>>(pIncl, pCnt, pBexc, pOffs);
    fill_kernel<<<edge_blocks, T, 0, sb>>>(pSrc, pDst, pOffs, pCsr, E);

    // join
    if (forked) {
        cudaEventRecord(eB, s2);
        cudaStreamWaitEvent((cudaStream_t)0, eB, 0);
    }

    // layer-1 aggregation + epilogue -> h
    agg1_kernel<<<warp_blocks, T>>>(pCsr, pOffs, pCnt, pPT, b1, pH);
    // layer-2 tensor-core GEMM  qu = h @ [w2l|w2r]
    gemm_tc_kernel<80, 80, 80><<<dim3(gemm_rows, 1), T, SMEM2>>>(
        pH, pWcat2, pPT, N);
    // layer-2 aggregation + epilogue -> out
    agg2_kernel<<<warp_blocks, T>>>(pCsr, pOffs, pCnt, pPT, b2, out);
}

// round 10
// speedup vs baseline: 1.4528x; 1.4528x over previous
#include <cuda_runtime.h>
#include <cstdint>

#define NN   50000
#define F    128
#define NCLS 40
#define MAXE 600000
#define SCB  512
#define NSB  ((NN + SCB - 1) / SCB)   // 98

// ---------------- scratch (__device__ globals; no allocations) -------------
__device__ float g_pt[NN * 256];       // layer1: [p|t] (stride 256); layer2: [q|u] (stride 80)
__device__ float g_h[NN * F];          // hidden activations
__device__ float g_wt1_hi[256 * F];    // [w1l|w1r]^T hi  (n-major: [n][k])
__device__ float g_wt1_lo[256 * F];
__device__ float g_wt2_hi[80 * F];     // [w2l|w2r]^T hi
__device__ float g_wt2_lo[80 * F];
__device__ int g_src[MAXE], g_dst[MAXE], g_csr[MAXE];
__device__ int g_cnt[NN], g_offs[NN], g_incl[NN];
__device__ int g_bsum[NSB], g_bexc[NSB];
__device__ int g_mode32;

// ---------------------------------------------------------------------------
__device__ __forceinline__ uint2 f2tf32p(float a) {
    uint2 r;
    asm("cvt.rna.tf32.f32 %0, %1;" : "=r"(r.x) : "f"(a));
    float t = a - __uint_as_float(r.x);
    asm("cvt.rna.tf32.f32 %0, %1;" : "=r"(r.y) : "f"(t));
    return r;
}

__global__ void detect_kernel(const void* ei) {
    if (threadIdx.x == 0 && blockIdx.x == 0) {
        const long long* p = (const long long*)ei;
        int m32 = 0;
        for (int i = 0; i < 16; i++) {
            long long v = p[i];
            if (v < 0 || v >= NN) { m32 = 1; break; }
        }
        g_mode32 = m32;
    }
}

__global__ void zero_int_kernel(int4* a, int n4) {
    int i = blockIdx.x * blockDim.x + threadIdx.x;
    int stride = gridDim.x * blockDim.x;
    int4 z = make_int4(0, 0, 0, 0);
    for (; i < n4; i += stride) a[i] = z;
}

// Build transposed, tf32-split weight matrices: [n][k] layout.
__global__ void build_wcat_kernel(const float* __restrict__ w1l,
                                  const float* __restrict__ w1r,
                                  const float* __restrict__ w2l,
                                  const float* __restrict__ w2r,
                                  float* __restrict__ wt1_hi, float* __restrict__ wt1_lo,
                                  float* __restrict__ wt2_hi, float* __restrict__ wt2_lo) {
    int i = blockIdx.x * blockDim.x + threadIdx.x;
    if (i < 256 * F) {
        int n = i >> 7, k = i & 127;
        float v = (n < 128) ? w1l[k * 128 + n] : w1r[k * 128 + (n - 128)];
        uint2 p = f2tf32p(v);
        wt1_hi[i] = __uint_as_float(p.x);
        wt1_lo[i] = __uint_as_float(p.y);
    } else if (i < 256 * F + 80 * F) {
        int j = i - 256 * F;
        int n = j >> 7, k = j & 127;
        float v = (n < NCLS) ? w2l[k * NCLS + n] : w2r[k * NCLS + (n - NCLS)];
        uint2 p = f2tf32p(v);
        wt2_hi[j] = __uint_as_float(p.x);
        wt2_lo[j] = __uint_as_float(p.y);
    }
}

__global__ void hist_kernel(const void* __restrict__ ei,
                            int* __restrict__ src32, int* __restrict__ dst32,
                            int* __restrict__ cnt, int E) {
    const int mode32 = g_mode32;
    int stride = gridDim.x * blockDim.x;
    for (int e = blockIdx.x * blockDim.x + threadIdx.x; e < E; e += stride) {
        int s, d;
        if (mode32) {
            const int* p = (const int*)ei;
            s = p[e]; d = p[E + e];
        } else {
            const long long* p = (const long long*)ei;
            s = (int)p[e]; d = (int)p[E + e];
        }
        src32[e] = s;
        dst32[e] = d;
        atomicAdd(&cnt[d], 1);
    }
}

__global__ void scan1_kernel(const int* __restrict__ cnt,
                             int* __restrict__ incl, int* __restrict__ bsum) {
    __shared__ int sm[SCB];
    int t = threadIdx.x;
    int i = blockIdx.x * SCB + t;
    int v = (i < NN) ? cnt[i] : 0;
    sm[t] = v;
    __syncthreads();
    for (int off = 1; off < SCB; off <<= 1) {
        int x = (t >= off) ? sm[t - off] : 0;
        __syncthreads();
        sm[t] += x;
        __syncthreads();
    }
    if (i < NN) incl[i] = sm[t];
    if (t == SCB - 1) bsum[blockIdx.x] = sm[t];
}

__global__ void scan2_kernel(const int* __restrict__ bsum, int* __restrict__ bexc) {
    __shared__ int sm[128];
    int t = threadIdx.x;
    int v = (t < NSB) ? bsum[t] : 0;
    sm[t] = v;
    __syncthreads();
    for (int off = 1; off < 128; off <<= 1) {
        int x = (t >= off) ? sm[t - off] : 0;
        __syncthreads();
        sm[t] += x;
        __syncthreads();
    }
    if (t < NSB) bexc[t] = sm[t] - v;
}

__global__ void scan3_kernel(const int* __restrict__ incl,
                             const int* __restrict__ cnt,
                             const int* __restrict__ bexc,
                             int* __restrict__ offs) {
    int i = blockIdx.x * blockDim.x + threadIdx.x;
    if (i < NN) offs[i] = incl[i] - cnt[i] + bexc[i >> 9];
}

__global__ void fill_kernel(const int* __restrict__ src32,
                            const int* __restrict__ dst32,
                            int* __restrict__ offs, int* __restrict__ csr, int E) {
    int stride = gridDim.x * blockDim.x;
    for (int e = blockIdx.x * blockDim.x + threadIdx.x; e < E; e += stride) {
        int d = dst32[e];
        int slot = atomicAdd(&offs[d], 1);
        csr[slot] = src32[e];
    }
}

// ---------------------------------------------------------------------------
// 3xTF32 tensor-core GEMM, conversions hoisted out of the MMA loop.
// A hi/lo computed once per tile into separate float smem arrays (vector
// float4 stores); B hi/lo pre-converted in GLOBAL ([n][k] transposed) and
// copied straight into smem. Inner loop = pure LDS.32 + HMMA.
// K staged in 4 slices of 32; KP=36 (banks 4g+tig -> conflict-free frags).
// 8 warps: 4(m) x 2(n); warp tile 32 x BN/2; mma.m16n8k8; 3-term 3xTF32.
// NOTE: tf32 A/B operands must be .b32 registers ("r" constraint).
#define MMA_TF32(c, a0, a1, a2, a3, b0, b1)                                 \
    asm volatile(                                                           \
        "mma.sync.aligned.m16n8k8.row.col.f32.tf32.tf32.f32 "               \
        "{%0,%1,%2,%3},{%4,%5,%6,%7},{%8,%9},{%0,%1,%2,%3};"                \
        : "+f"((c)[0]), "+f"((c)[1]), "+f"((c)[2]), "+f"((c)[3])            \
        : "r"(a0), "r"(a1), "r"(a2), "r"(a3), "r"(b0), "r"(b1))

template <int BN, int SWC>
__global__ __launch_bounds__(256, 2)
void gemm_tc_kernel(const float* __restrict__ A,
                    const float* __restrict__ Bt_hi,   // [BNtot][128]
                    const float* __restrict__ Bt_lo,
                    float* __restrict__ C,
                    int Nrows) {
    constexpr int NWT = BN / 16;
    constexpr int KP = 36;
    extern __shared__ float sm[];
    float* As_hi = sm;                     // [128][KP]
    float* As_lo = sm + 128 * KP;
    float* Bs_hi = sm + 2 * 128 * KP;      // [BN][KP]
    float* Bs_lo = Bs_hi + BN * KP;
    // uint32 views for tf32 fragment loads (mma needs .b32 regs)
    const uint32_t* uAs_hi = (const uint32_t*)As_hi;
    const uint32_t* uAs_lo = (const uint32_t*)As_lo;
    const uint32_t* uBs_hi = (const uint32_t*)Bs_hi;
    const uint32_t* uBs_lo = (const uint32_t*)Bs_lo;

    int tid = threadIdx.x;
    int lane = tid & 31;
    int warp = tid >> 5;
    int g = lane >> 2, tig = lane & 3;
    int warpRow = warp & 3, warpCol = warp >> 2;
    int brow = blockIdx.x * 128;
    int colbase = blockIdx.y * 128;

    float acc[2][NWT][4];
#pragma unroll
    for (int mt = 0; mt < 2; mt++)
#pragma unroll
        for (int nt = 0; nt < NWT; nt++)
#pragma unroll
            for (int j = 0; j < 4; j++) acc[mt][nt][j] = 0.0f;

#pragma unroll
    for (int ks = 0; ks < 4; ks++) {
        int kc = ks * 32;
        if (ks) __syncthreads();
        // --- A slice (128 x 32): load float4, split, vector-store hi/lo
#pragma unroll
        for (int p = 0; p < 4; p++) {
            int idx = tid + p * 256;          // 0..1023
            int m = idx >> 3;
            int kq = (idx & 7) << 2;
            float4 v = make_float4(0.f, 0.f, 0.f, 0.f);
            if (brow + m < Nrows)
                v = *(const float4*)(A + (size_t)(brow + m) * F + kc + kq);
            uint2 px = f2tf32p(v.x), py = f2tf32p(v.y);
            uint2 pz = f2tf32p(v.z), pw = f2tf32p(v.w);
            float4 hv, lv;
            hv.x = __uint_as_float(px.x); lv.x = __uint_as_float(px.y);
            hv.y = __uint_as_float(py.x); lv.y = __uint_as_float(py.y);
            hv.z = __uint_as_float(pz.x); lv.z = __uint_as_float(pz.y);
            hv.w = __uint_as_float(pw.x); lv.w = __uint_as_float(pw.y);
            *(float4*)(As_hi + m * KP + kq) = hv;
            *(float4*)(As_lo + m * KP + kq) = lv;
        }
        // --- B slice (BN x 32): straight copy from pre-split transposed global
        constexpr int BF4 = BN * 8;           // float4 count
#pragma unroll
        for (int p = 0; p < (BF4 + 255) / 256; p++) {
            int idx = tid + p * 256;
            if (idx < BF4) {
                int n = idx >> 3;
                int kq = (idx & 7) << 2;
                size_t go = (size_t)(colbase + n) * F + kc + kq;
                *(float4*)(Bs_hi + n * KP + kq) = *(const float4*)(Bt_hi + go);
                *(float4*)(Bs_lo + n * KP + kq) = *(const float4*)(Bt_lo + go);
            }
        }
        __syncthreads();

#pragma unroll
        for (int k8 = 0; k8 < 4; k8++) {
            int kb = k8 * 8;
            uint32_t ah[2][4], al[2][4];
#pragma unroll
            for (int mt = 0; mt < 2; mt++) {
                int ro = (warpRow * 32 + mt * 16 + g) * KP + kb;
                ah[mt][0] = uAs_hi[ro + tig];
                ah[mt][1] = uAs_hi[ro + 8 * KP + tig];
                ah[mt][2] = uAs_hi[ro + tig + 4];
                ah[mt][3] = uAs_hi[ro + 8 * KP + tig + 4];
                al[mt][0] = uAs_lo[ro + tig];
                al[mt][1] = uAs_lo[ro + 8 * KP + tig];
                al[mt][2] = uAs_lo[ro + tig + 4];
                al[mt][3] = uAs_lo[ro + 8 * KP + tig + 4];
            }
#pragma unroll
            for (int nt = 0; nt < NWT; nt++) {
                int bo = (warpCol * (BN / 2) + nt * 8 + g) * KP + kb;
                uint32_t bh0 = uBs_hi[bo + tig];
                uint32_t bh1 = uBs_hi[bo + tig + 4];
                uint32_t bl0 = uBs_lo[bo + tig];
                uint32_t bl1 = uBs_lo[bo + tig + 4];
#pragma unroll
                for (int mt = 0; mt < 2; mt++) {
                    MMA_TF32(acc[mt][nt], ah[mt][0], ah[mt][1], ah[mt][2], ah[mt][3], bh0, bh1);
                    MMA_TF32(acc[mt][nt], ah[mt][0], ah[mt][1], ah[mt][2], ah[mt][3], bl0, bl1);
                    MMA_TF32(acc[mt][nt], al[mt][0], al[mt][1], al[mt][2], al[mt][3], bh0, bh1);
                }
            }
        }
    }

    // epilogue: c0,c1 = (row, 2tig..2tig+1), c2,c3 = (row+8, ...)
#pragma unroll
    for (int mt = 0; mt < 2; mt++) {
#pragma unroll
        for (int nt = 0; nt < NWT; nt++) {
            int row0 = brow + warpRow * 32 + mt * 16 + g;
            int col = colbase + warpCol * (BN / 2) + nt * 8 + 2 * tig;
            if (row0 < Nrows) {
                float2 v = make_float2(acc[mt][nt][0], acc[mt][nt][1]);
                *(float2*)(C + (size_t)row0 * SWC + col) = v;
            }
            if (row0 + 8 < Nrows) {
                float2 v = make_float2(acc[mt][nt][2], acc[mt][nt][3]);
                *(float2*)(C + (size_t)(row0 + 8) * SWC + col) = v;
            }
        }
    }
}

// ---------------------------------------------------------------------------
// Layer-1 aggregation + epilogue: h[n] = relu(mean_{s in N(n)} p[s] + t[n] + b1)
__global__ void agg1_kernel(const int* __restrict__ csr,
                            const int* __restrict__ offs,
                            const int* __restrict__ cnt,
                            const float* __restrict__ pt,
                            const float* __restrict__ b1,
                            float* __restrict__ h) {
    int gw = (blockIdx.x * blockDim.x + threadIdx.x) >> 5;
    int lane = threadIdx.x & 31;
    if (gw >= NN) return;
    int dg = cnt[gw];
    int beg = offs[gw] - dg;
    float4 acc0 = make_float4(0.f, 0.f, 0.f, 0.f);
    float4 acc1 = make_float4(0.f, 0.f, 0.f, 0.f);
    int i = 0;
    for (; i + 4 <= dg; i += 4) {
        int s0 = __ldg(&csr[beg + i]);
        int s1 = __ldg(&csr[beg + i + 1]);
        int s2 = __ldg(&csr[beg + i + 2]);
        int s3 = __ldg(&csr[beg + i + 3]);
        float4 v0 = *(const float4*)(pt + (long long)s0 * 256 + lane * 4);
        float4 v1 = *(const float4*)(pt + (long long)s1 * 256 + lane * 4);
        float4 v2 = *(const float4*)(pt + (long long)s2 * 256 + lane * 4);
        float4 v3 = *(const float4*)(pt + (long long)s3 * 256 + lane * 4);
        acc0.x += v0.x + v1.x; acc0.y += v0.y + v1.y;
        acc0.z += v0.z + v1.z; acc0.w += v0.w + v1.w;
        acc1.x += v2.x + v3.x; acc1.y += v2.y + v3.y;
        acc1.z += v2.z + v3.z; acc1.w += v2.w + v3.w;
    }
    for (; i < dg; i++) {
        int s = __ldg(&csr[beg + i]);
        float4 v = *(const float4*)(pt + (long long)s * 256 + lane * 4);
        acc0.x += v.x; acc0.y += v.y; acc0.z += v.z; acc0.w += v.w;
    }
    float inv = 1.0f / fmaxf((float)dg, 1.0f);
    float4 t = *(const float4*)(pt + (long long)gw * 256 + 128 + lane * 4);
    float4 bb = *(const float4*)(b1 + lane * 4);
    float4 r;
    r.x = fmaxf((acc0.x + acc1.x) * inv + t.x + bb.x, 0.f);
    r.y = fmaxf((acc0.y + acc1.y) * inv + t.y + bb.y, 0.f);
    r.z = fmaxf((acc0.z + acc1.z) * inv + t.z + bb.z, 0.f);
    r.w = fmaxf((acc0.w + acc1.w) * inv + t.w + bb.w, 0.f);
    *(float4*)(h + (long long)gw * F + lane * 4) = r;
}

// Layer-2: out[n] = mean q[s] + u[n] + b2. qu stride 80: q=0:40, u=40:80.
__global__ void agg2_kernel(const int* __restrict__ csr,
                            const int* __restrict__ offs,
                            const int* __restrict__ cnt,
                            const float* __restrict__ qu,
                            const float* __restrict__ b2,
                            float* __restrict__ out) {
    int gw = (blockIdx.x * blockDim.x + threadIdx.x) >> 5;
    int lane = threadIdx.x & 31;
    if (gw >= NN) return;
    int dg = cnt[gw];
    int beg = offs[gw] - dg;
    if (lane < 10) {
        float4 acc0 = make_float4(0.f, 0.f, 0.f, 0.f);
        float4 acc1 = make_float4(0.f, 0.f, 0.f, 0.f);
        int i = 0;
        for (; i + 4 <= dg; i += 4) {
            int s0 = __ldg(&csr[beg + i]);
            int s1 = __ldg(&csr[beg + i + 1]);
            int s2 = __ldg(&csr[beg + i + 2]);
            int s3 = __ldg(&csr[beg + i + 3]);
            float4 v0 = *(const float4*)(qu + (long long)s0 * 80 + lane * 4);
            float4 v1 = *(const float4*)(qu + (long long)s1 * 80 + lane * 4);
            float4 v2 = *(const float4*)(qu + (long long)s2 * 80 + lane * 4);
            float4 v3 = *(const float4*)(qu + (long long)s3 * 80 + lane * 4);
            acc0.x += v0.x + v1.x; acc0.y += v0.y + v1.y;
            acc0.z += v0.z + v1.z; acc0.w += v0.w + v1.w;
            acc1.x += v2.x + v3.x; acc1.y += v2.y + v3.y;
            acc1.z += v2.z + v3.z; acc1.w += v2.w + v3.w;
        }
        for (; i < dg; i++) {
            int s = __ldg(&csr[beg + i]);
            float4 v = *(const float4*)(qu + (long long)s * 80 + lane * 4);
            acc0.x += v.x; acc0.y += v.y; acc0.z += v.z; acc0.w += v.w;
        }
        float inv = 1.0f / fmaxf((float)dg, 1.0f);
        float4 uv = *(const float4*)(qu + (long long)gw * 80 + NCLS + lane * 4);
        float4 bb = *(const float4*)(b2 + lane * 4);
        float4 r;
        r.x = (acc0.x + acc1.x) * inv + uv.x + bb.x;
        r.y = (acc0.y + acc1.y) * inv + uv.y + bb.y;
        r.z = (acc0.z + acc1.z) * inv + uv.z + bb.z;
        r.w = (acc0.w + acc1.w) * inv + uv.w + bb.w;
        *(float4*)(out + (long long)gw * NCLS + lane * 4) = r;
    }
}

// ---------------------------------------------------------------------------
extern "C" void kernel_launch(void* const* d_in, const int* in_sizes, int n_in,
                              void* d_out, int out_size) {
    const float* x   = (const float*)d_in[0];
    const void*  ei  = d_in[1];
    const float* w1l = (const float*)d_in[2];
    const float* w1r = (const float*)d_in[3];
    const float* b1  = (const float*)d_in[4];
    const float* w2l = (const float*)d_in[5];
    const float* w2r = (const float*)d_in[6];
    const float* b2  = (const float*)d_in[7];
    float* out = (float*)d_out;

    int E = in_sizes[1] / 2;
    int N = in_sizes[0] / F;   // 50000

    float *pPT, *pH, *pW1h, *pW1l, *pW2h, *pW2l;
    int *pSrc, *pDst, *pCsr, *pCnt, *pOffs, *pIncl, *pBsum, *pBexc;
    cudaGetSymbolAddress((void**)&pPT,  g_pt);
    cudaGetSymbolAddress((void**)&pH,   g_h);
    cudaGetSymbolAddress((void**)&pW1h, g_wt1_hi);
    cudaGetSymbolAddress((void**)&pW1l, g_wt1_lo);
    cudaGetSymbolAddress((void**)&pW2h, g_wt2_hi);
    cudaGetSymbolAddress((void**)&pW2l, g_wt2_lo);
    cudaGetSymbolAddress((void**)&pSrc, g_src);
    cudaGetSymbolAddress((void**)&pDst, g_dst);
    cudaGetSymbolAddress((void**)&pCsr, g_csr);
    cudaGetSymbolAddress((void**)&pCnt, g_cnt);
    cudaGetSymbolAddress((void**)&pOffs, g_offs);
    cudaGetSymbolAddress((void**)&pIncl, g_incl);
    cudaGetSymbolAddress((void**)&pBsum, g_bsum);
    cudaGetSymbolAddress((void**)&pBexc, g_bexc);

    const int T = 256;
    int gemm_rows = (N + 127) / 128;          // 391
    int edge_blocks = (E + T - 1) / T;        // 2344
    int warp_blocks = (N * 32 + T - 1) / T;   // 6250

    // dynamic smem opt-in
    const int SMEM1 = (2 * 128 + 2 * 128) * 36 * 4;   // 73728
    const int SMEM2 = (2 * 128 + 2 * 80) * 36 * 4;    // 59904
    cudaFuncSetAttribute(gemm_tc_kernel<128, 256>,
                         cudaFuncAttributeMaxDynamicSharedMemorySize, SMEM1);
    cudaFuncSetAttribute(gemm_tc_kernel<80, 80>,
                         cudaFuncAttributeMaxDynamicSharedMemorySize, SMEM2);

    // Fork-join resources (host-side only; created per call, not destroyed).
    cudaStream_t s2 = 0;
    cudaEvent_t eA = 0, eB = 0;
    bool forked = (cudaStreamCreateWithFlags(&s2, cudaStreamNonBlocking) == cudaSuccess);
    if (forked) forked = (cudaEventCreateWithFlags(&eA, cudaEventDisableTiming) == cudaSuccess);
    if (forked) forked = (cudaEventCreateWithFlags(&eB, cudaEventDisableTiming) == cudaSuccess);
    cudaStream_t sb = forked ? s2 : (cudaStream_t)0;

    // --- main stream: 1 detect, 2 zero, 3 wcat ---
    detect_kernel<<<1, 32>>>(ei);
    zero_int_kernel<<<64, T>>>((int4*)pCnt, NN / 4 + 1);
    build_wcat_kernel<<<(256 * F + 80 * F + T - 1) / T, T>>>(
        w1l, w1r, w2l, w2r, pW1h, pW1l, pW2h, pW2l);

    // fork
    if (forked) {
        cudaEventRecord(eA, 0);
        cudaStreamWaitEvent(s2, eA, 0);
    }

    // 4: layer-1 tensor-core GEMM (profiled launch)
    gemm_tc_kernel<128, 256><<<dim3(gemm_rows, 2), T, SMEM1>>>(
        x, pW1h, pW1l, pPT, N);

    // CSR chain on branch stream (overlaps gemm1)
    hist_kernel<<<edge_blocks, T, 0, sb>>>(ei, pSrc, pDst, pCnt, E);
    scan1_kernel<<<NSB, SCB, 0, sb>>>(pCnt, pIncl, pBsum);
    scan2_kernel<<<1, 128, 0, sb>>>(pBsum, pBexc);
    scan3_kernel<<<(NN + T - 1) / T, T, 0, sb>>>(pIncl, pCnt, pBexc, pOffs);
    fill_kernel<<<edge_blocks, T, 0, sb>>>(pSrc, pDst, pOffs, pCsr, E);

    // join
    if (forked) {
        cudaEventRecord(eB, s2);
        cudaStreamWaitEvent((cudaStream_t)0, eB, 0);
    }

    // layer-1 aggregation + epilogue -> h
    agg1_kernel<<<warp_blocks, T>>>(pCsr, pOffs, pCnt, pPT, b1, pH);
    // layer-2 tensor-core GEMM  qu = h @ [w2l|w2r]
    gemm_tc_kernel<80, 80><<<dim3(gemm_rows, 1), T, SMEM2>>>(
        pH, pW2h, pW2l, pPT, N);
    // layer-2 aggregation + epilogue -> out
    agg2_kernel<<<warp_blocks, T>>>(pCsr, pOffs, pCnt, pPT, b2, out);
}